// round 11
// baseline (speedup 1.0000x reference)
#include <cuda_runtime.h>
#include <cstdint>
#include <cstddef>

// Problem constants
#define NROWS 32768          // B*T
#define DDIM  256
#define KCODES 1024

// Output layout (float32 concat of reference tuple)
#define Q_OFF    ((size_t)0)
#define LOSS_OFF ((size_t)8388608)
#define IDX_OFF  ((size_t)8388609)
#define CS_OFF   ((size_t)8421377)
#define EMAW_OFF ((size_t)8422401)
#define EMB_OFF  ((size_t)8684545)

#define DECAY 0.99f
#define OMD   ((float)(1.0 - 0.99))
#define EPS   1e-5f
#define KEPS  (1024.0f * 1e-5f)

// sound margin: tf32(rna) score error <= 2*2^-10*||z||*||e|| ~= 7e-4; margin > 2*ERR
#define MARGIN 2.5e-3f

// ---------------------------------------------------------------------------
// Scratch (allocation-free rule: __device__ globals)
__device__ __align__(16) float g_e2[KCODES];
__device__ __align__(16) float g_zn[NROWS];
__device__ float g_counts[KCODES];
__device__ float g_dw[KCODES * DDIM];
__device__ float g_loss;
__device__ float g_cs[KCODES];
__device__ __align__(16) float g_scores[(size_t)NROWS * KCODES];   // 128 MB
// fragment-ordered tf32 operands
__device__ __align__(16) uint4 g_ef[16 * 32 * 4 * 32];             // 1 MB  : e frags
__device__ __align__(16) uint4 g_zf[(NROWS / 128) * 8192];         // 32 MB : z frags

// ---------------------------------------------------------------------------
__device__ __forceinline__ uint32_t f2tf(float x) {
    uint32_t u;
    asm("cvt.rna.tf32.f32 %0, %1;" : "=r"(u) : "f"(x));
    return u;
}

// mma.sync m16n8k8 row.col f32.tf32.tf32.f32 (standard PTX, works on sm_103)
__device__ __forceinline__ void mma_tf32(float* d, uint4 a, uint32_t b0, uint32_t b1) {
    asm volatile(
        "mma.sync.aligned.m16n8k8.row.col.f32.tf32.tf32.f32 "
        "{%0,%1,%2,%3}, {%4,%5,%6,%7}, {%8,%9}, {%0,%1,%2,%3};"
        : "+f"(d[0]), "+f"(d[1]), "+f"(d[2]), "+f"(d[3])
        : "r"(a.x), "r"(a.y), "r"(a.z), "r"(a.w), "r"(b0), "r"(b1));
}

// ======================= small prep kernels ================================
__global__ void vq_init() {
    int i = blockIdx.x * blockDim.x + threadIdx.x;
    if (i < KCODES * DDIM) g_dw[i] = 0.0f;
    if (i < KCODES) g_counts[i] = 0.0f;
    if (i == 0) g_loss = 0.0f;
}

__global__ void vq_e2(const float* __restrict__ emb) {
    int k = blockIdx.x;
    float v = emb[k * DDIM + threadIdx.x];
    v *= v;
    for (int off = 16; off; off >>= 1) v += __shfl_down_sync(0xffffffffu, v, off);
    __shared__ float red[8];
    int lane = threadIdx.x & 31, wid = threadIdx.x >> 5;
    if (lane == 0) red[wid] = v;
    __syncthreads();
    if (threadIdx.x == 0) {
        float t = 0.f;
        #pragma unroll
        for (int w = 0; w < 8; w++) t += red[w];
        g_e2[k] = t;
    }
}

__global__ void vq_zn(const float* __restrict__ z) {
    int r = blockIdx.x * 128 + threadIdx.x;
    const float4* p = (const float4*)(z + (size_t)r * DDIM);
    float s = 0.f;
    #pragma unroll
    for (int i = 0; i < 64; i++) {
        float4 v = p[i];
        s = fmaf(v.x, v.x, s); s = fmaf(v.y, v.y, s);
        s = fmaf(v.z, v.z, s); s = fmaf(v.w, v.w, s);
    }
    g_zn[r] = s;
}

// Build e fragments: g_ef[cchunk16][kc32][ntp4][lane32] uint4
// comps: [0]=e[cA][k+t] [1]=e[cA][k+t+4] [2]=e[cB][k+t] [3]=e[cB][k+t+4]
// cA = cchunk*64+ntp*16+g, cB = cA+8, lane = g*4+t
__global__ void vq_ef(const float* __restrict__ emb) {
    int c = blockIdx.x;            // 1024
    int d = threadIdx.x;           // 256
    int cchunk = c >> 6, cc = c & 63;
    int ntp = cc >> 4, ccc = cc & 15;
    int b_hi = ccc >> 3, g = ccc & 7;
    int kc = d >> 3, din = d & 7;
    int c_hi = din >> 2, t = din & 3;
    int lane = g * 4 + t;
    int comp = b_hi * 2 + c_hi;
    int entry = ((cchunk * 32 + kc) * 4 + ntp) * 32 + lane;
    ((uint32_t*)g_ef)[entry * 4 + comp] = f2tf(emb[c * DDIM + d]);
}

// Build z fragments: g_zf[rblk][w2mt? -> (((rblk*4+w)*2+mt)*32+kc)*32+lane] uint4
// comps: [0]=(c_lo,r_lo) [1]=(c_lo,r_hi) [2]=(c_hi,r_lo) [3]=(c_hi,r_hi)
__global__ void vq_zf(const float* __restrict__ z) {
    int rid = blockIdx.x;                          // 16384
    int r = ((rid >> 3) << 4) | (rid & 7);         // rows with (r&15) < 8
    int d = threadIdx.x;                           // 256
    int rblk = r >> 7, rr = r & 127;
    int w = rr >> 5, rl = rr & 31;
    int mt = rl >> 4, g = rl & 7;
    int kc = d >> 3, din = d & 7;
    int c_hi = din >> 2, t = din & 3;
    int lane = g * 4 + t;
    int entry = (((rblk * 4 + w) * 2 + mt) * 32 + kc) * 32 + lane;
    uint2 v;
    v.x = f2tf(z[(size_t)r * DDIM + d]);           // r_lo (comp c_hi*2)
    v.y = f2tf(z[(size_t)(r + 8) * DDIM + d]);     // r_hi (comp c_hi*2+1)
    ((uint2*)g_zf)[entry * 2 + c_hi] = v;
}

// ======================= mma.sync TF32 score GEMM ==========================
// CTA: 128 thr (4 warps), M=128 rows. Warp w: rows w*32..w*32+31.
// Warp tile per cchunk: 32 rows x 64 codes (2 mt x 8 nt), 64 accum regs.
#define GEMM_SMEM ((8192 + 1024) * 16)   // zf 128KB + ebuf 16KB = 147456 B

__global__ __launch_bounds__(128, 1)
void vq_gemm(float* __restrict__ scores) {
    extern __shared__ uint4 smem[];
    uint4* zf = smem;                     // 8192 uint4
    uint4* eb = smem + 8192;              // 1024 uint4 (one kc-stage: 8 kc x 4 ntp x 32)

    const int tid  = threadIdx.x;
    const int lane = tid & 31;
    const int w    = tid >> 5;
    const int g    = lane >> 2;
    const int t    = lane & 3;
    const int rblk = blockIdx.x;
    const int row0 = rblk * 128;

    // coalesced copy of this block's z fragments (128 KB)
    const uint4* zsrc = g_zf + (size_t)rblk * 8192;
    #pragma unroll
    for (int j = 0; j < 64; j++) zf[tid + j * 128] = zsrc[tid + j * 128];

    // prefetch ef slice 0 (g_ef is consumed linearly, 64 slices of 1024 uint4)
    uint4 pre[8];
    #pragma unroll
    for (int j = 0; j < 8; j++) pre[j] = g_ef[tid + j * 128];

    // per-row norms for this warp's rows
    float znv[2][2];
    znv[0][0] = g_zn[row0 + w * 32 + g];
    znv[0][1] = g_zn[row0 + w * 32 + g + 8];
    znv[1][0] = g_zn[row0 + w * 32 + g + 16];
    znv[1][1] = g_zn[row0 + w * 32 + g + 24];

    float acc[2][8][4];
    #pragma unroll
    for (int mt = 0; mt < 2; mt++)
        #pragma unroll
        for (int nt = 0; nt < 8; nt++)
            #pragma unroll
            for (int q = 0; q < 4; q++) acc[mt][nt][q] = 0.f;

    int st_lin = 0;
    for (int cchunk = 0; cchunk < 16; cchunk++) {
        for (int s = 0; s < 4; s++) {
            __syncthreads();                       // prior stage fully consumed
            #pragma unroll
            for (int j = 0; j < 8; j++) eb[tid + j * 128] = pre[j];
            __syncthreads();
            if (st_lin < 63) {
                const uint4* nsrc = g_ef + (st_lin + 1) * 1024;
                #pragma unroll
                for (int j = 0; j < 8; j++) pre[j] = nsrc[tid + j * 128];
            }
            #pragma unroll
            for (int kc = 0; kc < 8; kc++) {
                int kg = s * 8 + kc;
                uint4 a0 = zf[((w * 2 + 0) * 32 + kg) * 32 + lane];
                uint4 a1 = zf[((w * 2 + 1) * 32 + kg) * 32 + lane];
                #pragma unroll
                for (int ntp = 0; ntp < 4; ntp++) {
                    uint4 b = eb[(kc * 4 + ntp) * 32 + lane];
                    mma_tf32(acc[0][2 * ntp],     a0, b.x, b.y);
                    mma_tf32(acc[0][2 * ntp + 1], a0, b.z, b.w);
                    mma_tf32(acc[1][2 * ntp],     a1, b.x, b.y);
                    mma_tf32(acc[1][2 * ntp + 1], a1, b.z, b.w);
                }
            }
            st_lin++;
        }
        // epilogue: scores = fl( fl(zn+e2) - fl(2*dot) ), reset accum
        #pragma unroll
        for (int mt = 0; mt < 2; mt++) {
            size_t rowA = (size_t)(row0 + w * 32 + mt * 16 + g);
            #pragma unroll
            for (int nt = 0; nt < 8; nt++) {
                int col = cchunk * 64 + nt * 8 + t * 2;
                float2 e2v = *(const float2*)&g_e2[col];
                float* a = acc[mt][nt];
                float2 sA, sB;
                sA.x = __fsub_rn(__fadd_rn(znv[mt][0], e2v.x), __fmul_rn(2.f, a[0]));
                sA.y = __fsub_rn(__fadd_rn(znv[mt][0], e2v.y), __fmul_rn(2.f, a[1]));
                sB.x = __fsub_rn(__fadd_rn(znv[mt][1], e2v.x), __fmul_rn(2.f, a[2]));
                sB.y = __fsub_rn(__fadd_rn(znv[mt][1], e2v.y), __fmul_rn(2.f, a[3]));
                *(float2*)&scores[rowA * KCODES + col] = sA;
                *(float2*)&scores[(rowA + 8) * KCODES + col] = sB;
                a[0] = a[1] = a[2] = a[3] = 0.f;
            }
        }
    }
}

// ============ argmin + exact rescore + fused row epilogue ==================
__global__ __launch_bounds__(256)
void vq_select(const float* __restrict__ z, const float* __restrict__ emb,
               float* __restrict__ out) {
    const int lane = threadIdx.x & 31;
    const int w    = threadIdx.x >> 5;
    const int row  = blockIdx.x * 8 + w;

    const float4* srow = (const float4*)(g_scores + (size_t)row * KCODES);
    float4 v[8];
    float bm = 3.402823466e38f; int bi = 0;
    #pragma unroll
    for (int i = 0; i < 8; i++) {
        v[i] = srow[i * 32 + lane];
        int c0 = (i * 32 + lane) * 4;
        if (v[i].x < bm) { bm = v[i].x; bi = c0; }
        if (v[i].y < bm) { bm = v[i].y; bi = c0 + 1; }
        if (v[i].z < bm) { bm = v[i].z; bi = c0 + 2; }
        if (v[i].w < bm) { bm = v[i].w; bi = c0 + 3; }
    }
    for (int off = 16; off; off >>= 1) {
        float ov = __shfl_down_sync(0xffffffffu, bm, off);
        int   oi = __shfl_down_sync(0xffffffffu, bi, off);
        if (ov < bm || (ov == bm && oi < bi)) { bm = ov; bi = oi; }
    }
    const float thr = __shfl_sync(0xffffffffu, bm, 0) + MARGIN;

    const float4* zp = (const float4*)(z + (size_t)row * DDIM);
    const float4 z0 = zp[lane * 2], z1 = zp[lane * 2 + 1];
    const float a_norm = g_zn[row];

    float bestsc = 3.402823466e38f; int bestidx = 0x7fffffff;
    #pragma unroll 1
    for (int i = 0; i < 8; i++) {
        float sv[4] = { v[i].x, v[i].y, v[i].z, v[i].w };
        #pragma unroll 1
        for (int c = 0; c < 4; c++) {
            int code = (i * 32 + lane) * 4 + c;
            unsigned m = __ballot_sync(0xffffffffu, sv[c] <= thr);
            while (m) {
                int src = __ffs(m) - 1; m &= m - 1;
                int cc = __shfl_sync(0xffffffffu, code, src);
                const float4* ep = (const float4*)(emb + (size_t)cc * DDIM);
                float4 e0 = ep[lane * 2], e1 = ep[lane * 2 + 1];
                float p = 0.f;
                p = fmaf(z0.x, e0.x, p); p = fmaf(z0.y, e0.y, p);
                p = fmaf(z0.z, e0.z, p); p = fmaf(z0.w, e0.w, p);
                p = fmaf(z1.x, e1.x, p); p = fmaf(z1.y, e1.y, p);
                p = fmaf(z1.z, e1.z, p); p = fmaf(z1.w, e1.w, p);
                for (int o = 16; o; o >>= 1) p += __shfl_xor_sync(0xffffffffu, p, o);
                float sce = __fsub_rn(__fadd_rn(a_norm, g_e2[cc]), __fmul_rn(2.f, p));
                if (sce < bestsc || (sce == bestsc && cc < bestidx)) { bestsc = sce; bestidx = cc; }
            }
        }
    }
    const int code = bestidx;

    // fused row epilogue
    const float4* qp = (const float4*)(emb + (size_t)code * DDIM);
    float4 q0 = qp[lane * 2], q1 = qp[lane * 2 + 1];
    float4* oq = (float4*)(out + Q_OFF + (size_t)row * DDIM);
    oq[lane * 2] = q0; oq[lane * 2 + 1] = q1;
    float ls = 0.f;
    {
        float d;
        d = z0.x - q0.x; ls = fmaf(d, d, ls);
        d = z0.y - q0.y; ls = fmaf(d, d, ls);
        d = z0.z - q0.z; ls = fmaf(d, d, ls);
        d = z0.w - q0.w; ls = fmaf(d, d, ls);
        d = z1.x - q1.x; ls = fmaf(d, d, ls);
        d = z1.y - q1.y; ls = fmaf(d, d, ls);
        d = z1.z - q1.z; ls = fmaf(d, d, ls);
        d = z1.w - q1.w; ls = fmaf(d, d, ls);
    }
    for (int o = 16; o; o >>= 1) ls += __shfl_xor_sync(0xffffffffu, ls, o);
    int base = code * DDIM + lane * 8;
    atomicAdd(&g_dw[base + 0], z0.x); atomicAdd(&g_dw[base + 1], z0.y);
    atomicAdd(&g_dw[base + 2], z0.z); atomicAdd(&g_dw[base + 3], z0.w);
    atomicAdd(&g_dw[base + 4], z1.x); atomicAdd(&g_dw[base + 5], z1.y);
    atomicAdd(&g_dw[base + 6], z1.z); atomicAdd(&g_dw[base + 7], z1.w);
    if (lane == 0) {
        out[IDX_OFF + row] = (float)code;
        atomicAdd(&g_counts[code], 1.0f);
        atomicAdd(&g_loss, ls);
    }
}

// ======================= EMA finalize kernels ==============================
__global__ void vq_finalize(const float* __restrict__ ema_cs, float* __restrict__ out) {
    int k = threadIdx.x;  // 1024 threads
    float pre = ema_cs[k] * DECAY + OMD * g_counts[k];
    __shared__ float sred[32];
    float v = pre;
    int lane = k & 31, wid = k >> 5;
    for (int off = 16; off; off >>= 1) v += __shfl_down_sync(0xffffffffu, v, off);
    if (lane == 0) sred[wid] = v;
    __syncthreads();
    if (wid == 0) {
        float t = sred[lane];
        for (int off = 16; off; off >>= 1) t += __shfl_down_sync(0xffffffffu, t, off);
        if (lane == 0) sred[0] = t;
    }
    __syncthreads();
    float n = sred[0];
    float cs = (pre + EPS) / (n + KEPS) * n;
    out[CS_OFF + k] = cs;
    g_cs[k] = cs;
    if (k == 0) out[LOSS_OFF] = 0.25f * g_loss / (float)(NROWS * DDIM);
}

__global__ void vq_emaw(const float* __restrict__ ema_w, float* __restrict__ out) {
    int i = blockIdx.x * 256 + threadIdx.x;   // < K*D
    int k = i >> 8;
    float w = ema_w[i] * DECAY + OMD * g_dw[i];
    out[EMAW_OFF + i] = w;
    out[EMB_OFF + i] = w / g_cs[k];
}

// ---------------------------------------------------------------------------
extern "C" void kernel_launch(void* const* d_in, const int* in_sizes, int n_in,
                              void* d_out, int out_size) {
    const float* z      = (const float*)d_in[0];  // [32,1024,256]
    const float* emb    = (const float*)d_in[1];  // [1024,256]
    const float* ema_cs = (const float*)d_in[2];  // [1024]
    const float* ema_w  = (const float*)d_in[3];  // [1024,256]
    float* out = (float*)d_out;
    (void)in_sizes; (void)n_in; (void)out_size;

    cudaFuncSetAttribute(vq_gemm, cudaFuncAttributeMaxDynamicSharedMemorySize, GEMM_SMEM);

    vq_init<<<(KCODES * DDIM + 255) / 256, 256>>>();          // 1
    vq_e2<<<KCODES, 256>>>(emb);                              // 2
    vq_zn<<<NROWS / 128, 128>>>(z);                           // 3
    vq_ef<<<KCODES, 256>>>(emb);                              // 4
    vq_zf<<<NROWS / 2, 256>>>(z);                             // 5
    vq_gemm<<<NROWS / 128, 128, GEMM_SMEM>>>(g_scores);       // 6 <- ncu -s5 slot
    vq_select<<<NROWS / 8, 256>>>(z, emb, out);               // 7
    vq_finalize<<<1, 1024>>>(ema_cs, out);                    // 8
    vq_emaw<<<KCODES * DDIM / 256, 256>>>(ema_w, out);        // 9
}

// round 12
// speedup vs baseline: 10.8545x; 10.8545x over previous
#include <cuda_runtime.h>
#include <cstdint>
#include <cstddef>

// Problem constants
#define NROWS 32768          // B*T
#define DDIM  256
#define KCODES 1024

// Output layout (float32 concat of reference tuple)
#define Q_OFF    ((size_t)0)
#define LOSS_OFF ((size_t)8388608)
#define IDX_OFF  ((size_t)8388609)
#define CS_OFF   ((size_t)8421377)
#define EMAW_OFF ((size_t)8422401)
#define EMB_OFF  ((size_t)8684545)

#define DECAY 0.99f
#define OMD   ((float)(1.0 - 0.99))
#define EPS   1e-5f
#define KEPS  (1024.0f * 1e-5f)

// Main-kernel tiling: 32 rows/CTA, 4 warps, warp = 8 rows x 128 codes,
// thread = 8 rows x 4 codes (acc = 32 float2 = 64 regs).
#define BM 32
#define NTHR 128
#define ZS 34                 // zsp row stride in float2 (16B-aligned: 34*8=272=16*17)
#define DST 8                 // d2 per e-stage
#define NSTAGE 16             // stages per k-chunk (DST*NSTAGE = 128 d2)
#define NKC 8                 // 1024 codes / 128 per chunk

#define ZSP_F2 (128*ZS)       // 4352 float2 = 34816 B
#define EST_F2 (DST*128)      // 1024 float2 per stage buffer (8 KB)
#define SMEM_BYTES (ZSP_F2*8 + 2*EST_F2*8 + BM*4 + BM*4 + 4*4)   // 51472 B

// Scratch (allocation-free rule: __device__ globals)
__device__ __align__(16) float g_e2[KCODES];
__device__ float g_counts[KCODES];
__device__ float g_dw[KCODES * DDIM];
__device__ float g_loss;
__device__ float g_cs[KCODES];

// ---------------------------------------------------------------------------
// packed fp32x2 FMA (PTX-only pattern; doubles FFMA throughput on sm_103a)
__device__ __forceinline__ void ffma2(float2 &d, float2 a, float2 b) {
    unsigned long long dd = *reinterpret_cast<unsigned long long*>(&d);
    unsigned long long aa = *reinterpret_cast<unsigned long long*>(&a);
    unsigned long long bb = *reinterpret_cast<unsigned long long*>(&b);
    asm("fma.rn.f32x2 %0, %1, %2, %0;" : "+l"(dd) : "l"(aa), "l"(bb));
    d = *reinterpret_cast<float2*>(&dd);
}

// ---------------------------------------------------------------------------
__global__ void vq_init() {
    int i = blockIdx.x * blockDim.x + threadIdx.x;
    if (i < KCODES * DDIM) g_dw[i] = 0.0f;
    if (i < KCODES) g_counts[i] = 0.0f;
    if (i == 0) g_loss = 0.0f;
}

__global__ void vq_nop() {}   // keeps vq_main in the ncu -s5 profiling slot

__global__ void vq_e2(const float* __restrict__ emb) {
    int k = blockIdx.x;
    float v = emb[k * DDIM + threadIdx.x];
    v *= v;
    for (int off = 16; off; off >>= 1) v += __shfl_down_sync(0xffffffffu, v, off);
    __shared__ float red[8];
    int lane = threadIdx.x & 31, wid = threadIdx.x >> 5;
    if (lane == 0) red[wid] = v;
    __syncthreads();
    if (threadIdx.x == 0) {
        float t = 0.f;
        #pragma unroll
        for (int w = 0; w < 8; w++) t += red[w];
        g_e2[k] = t;
    }
}

// ---------------------------------------------------------------------------
// stage store: thread t owns chunk-code t; pre[j] covers d2 = 2j, 2j+1
__device__ __forceinline__ void sts_stage(float2* eb, int t, const float4* pre) {
    #pragma unroll
    for (int j = 0; j < 4; j++) {
        float4 v = pre[j];
        eb[(2 * j) * 128 + t]     = make_float2(v.x, v.y);
        eb[(2 * j + 1) * 128 + t] = make_float2(v.z, v.w);
    }
}

__global__ __launch_bounds__(NTHR, 3)
void vq_main(const float* __restrict__ z, const float* __restrict__ emb,
             float* __restrict__ outq, float* __restrict__ outidx) {
    extern __shared__ char smem_raw[];
    float2* zsp = (float2*)smem_raw;             // [128 d2][ZS] z tile, d-pair packed, transposed
    float2* esp = zsp + ZSP_F2;                  // 2 stage buffers of [DST][128 codes]
    int*   sidx = (int*)(esp + 2 * EST_F2);      // [BM]
    float* sa   = (float*)(sidx + BM);           // [BM] ||z_row||^2
    float* lred = sa + BM;                       // [4]

    const int tid  = threadIdx.x;
    const int lane = tid & 31;
    const int w    = tid >> 5;                   // warp -> rows w*8..w*8+7
    const int row0 = blockIdx.x * BM;
    const float4* zv4  = (const float4*)z;
    const float4* embv = (const float4*)emb;

    // --- load z tile transposed & d-pair packed ---------------------------
    for (int idx = tid; idx < BM * (DDIM / 4); idx += NTHR) {
        int m = idx >> 6;                        // row 0..31
        int f4 = idx & 63;
        float4 v = zv4[(size_t)(row0 + m) * 64 + f4];
        zsp[(2 * f4) * ZS + m]     = make_float2(v.x, v.y);
        zsp[(2 * f4 + 1) * ZS + m] = make_float2(v.z, v.w);
    }
    // prefetch e stage (kc=0, st=0): thread t -> code t, 4 float4
    float4 pre[4];
    #pragma unroll
    for (int j = 0; j < 4; j++) pre[j] = embv[(size_t)tid * 64 + j];
    __syncthreads();

    // store stage 0; compute ||z||^2 per row (warp-owned 8 rows)
    sts_stage(esp, tid, pre);
    #pragma unroll
    for (int i = 0; i < 8; i++) {
        int row = w * 8 + i;
        float s = 0.f;
        #pragma unroll
        for (int u = 0; u < 4; u++) {
            float2 p = zsp[(lane + u * 32) * ZS + row];
            s = fmaf(p.x, p.x, fmaf(p.y, p.y, s));
        }
        for (int off = 16; off; off >>= 1) s += __shfl_down_sync(0xffffffffu, s, off);
        if (lane == 0) sa[row] = s;
    }
    __syncthreads();
    float anr[8];
    #pragma unroll
    for (int i = 0; i < 8; i++) anr[i] = sa[w * 8 + i];

    // --- main loop --------------------------------------------------------
    float bestv[8]; int besti[8];
    #pragma unroll
    for (int i = 0; i < 8; i++) { bestv[i] = 3.402823466e38f; besti[i] = 0; }
    float2 acc[8][4];
    #pragma unroll
    for (int i = 0; i < 8; i++)
        #pragma unroll
        for (int j = 0; j < 4; j++) acc[i][j] = make_float2(0.f, 0.f);

    int buf = 0;
    #pragma unroll 1
    for (int kc = 0; kc < NKC; kc++) {
        #pragma unroll 1
        for (int st = 0; st < NSTAGE; st++) {
            bool hn = !(kc == NKC - 1 && st == NSTAGE - 1);
            if (hn) {
                int nkc = kc, nst = st + 1;
                if (nst == NSTAGE) { nst = 0; nkc++; }
                #pragma unroll
                for (int j = 0; j < 4; j++)
                    pre[j] = embv[(size_t)(nkc * 128 + tid) * 64 + nst * 4 + j];
            }
            const float2* eb = esp + buf * EST_F2;
            #pragma unroll
            for (int dd = 0; dd < DST; dd++) {
                // z: 8 rows (float2 each), identical across the warp (broadcast)
                const float2* zr = zsp + (st * DST + dd) * ZS + w * 8;
                float2 a2[8];
                #pragma unroll
                for (int i = 0; i < 8; i += 2) {
                    float4 t = *reinterpret_cast<const float4*>(zr + i);
                    a2[i]     = make_float2(t.x, t.y);
                    a2[i + 1] = make_float2(t.z, t.w);
                }
                // e: codes {2l,2l+1} and {64+2l,65+2l}: two contiguous 16B chunks
                const float2* er = eb + dd * 128;
                float4 t0 = *reinterpret_cast<const float4*>(er + lane * 2);
                float4 t1 = *reinterpret_cast<const float4*>(er + 64 + lane * 2);
                float2 b2[4] = { make_float2(t0.x, t0.y), make_float2(t0.z, t0.w),
                                 make_float2(t1.x, t1.y), make_float2(t1.z, t1.w) };
                #pragma unroll
                for (int i = 0; i < 8; i++)
                    #pragma unroll
                    for (int j = 0; j < 4; j++) ffma2(acc[i][j], a2[i], b2[j]);
            }
            __syncthreads();
            if (hn) {
                sts_stage(esp + (buf ^ 1) * EST_F2, tid, pre);
                buf ^= 1;
                __syncthreads();
            }
        }
        // scores for this k-chunk, replicating jax rounding:
        // dist = fl( fl(||z||^2 + ||e||^2) - fl(2*dot) )
        float2 e2lo = *reinterpret_cast<const float2*>(&g_e2[kc * 128 + 2 * lane]);
        float2 e2hi = *reinterpret_cast<const float2*>(&g_e2[kc * 128 + 64 + 2 * lane]);
        float e2a[4] = { e2lo.x, e2lo.y, e2hi.x, e2hi.y };
        int   cda[4] = { kc * 128 + 2 * lane, kc * 128 + 2 * lane + 1,
                         kc * 128 + 64 + 2 * lane, kc * 128 + 64 + 2 * lane + 1 };
        #pragma unroll
        for (int i = 0; i < 8; i++) {
            float an = anr[i];
            #pragma unroll
            for (int j = 0; j < 4; j++) {
                float dot = acc[i][j].x + acc[i][j].y;
                float t1 = an + e2a[j];
                float sc = t1 - 2.0f * dot;
                if (sc < bestv[i]) { bestv[i] = sc; besti[i] = cda[j]; }
                acc[i][j] = make_float2(0.f, 0.f);
            }
        }
    }

    // --- warp argmin reduce (min value, lowest index on ties) -------------
    #pragma unroll
    for (int i = 0; i < 8; i++) {
        float v = bestv[i]; int ix = besti[i];
        #pragma unroll
        for (int off = 16; off; off >>= 1) {
            float ov = __shfl_down_sync(0xffffffffu, v, off);
            int   oi = __shfl_down_sync(0xffffffffu, ix, off);
            if (ov < v || (ov == v && oi < ix)) { v = ov; ix = oi; }
        }
        if (lane == 0) {
            int row = w * 8 + i;
            sidx[row] = ix;
            outidx[row0 + row] = (float)ix;
        }
    }
    __syncthreads();

    // --- epilogue: quantized gather, loss, counts, dw scatter -------------
    float lsum = 0.f;
    const int d0 = tid * 2;   // 128 threads x 2 floats = DDIM
    for (int r = 0; r < BM; r++) {
        int code = sidx[r];
        size_t go = (size_t)(row0 + r) * DDIM + d0;
        float2 q  = *reinterpret_cast<const float2*>(&emb[(size_t)code * DDIM + d0]);
        float2 zv = *reinterpret_cast<const float2*>(&z[go]);
        *reinterpret_cast<float2*>(&outq[go]) = q;
        float dx = zv.x - q.x, dy = zv.y - q.y;
        lsum = fmaf(dx, dx, fmaf(dy, dy, lsum));
        atomicAdd(&g_dw[code * DDIM + d0], zv.x);
        atomicAdd(&g_dw[code * DDIM + d0 + 1], zv.y);
    }
    if (tid < BM) atomicAdd(&g_counts[sidx[tid]], 1.0f);

    for (int off = 16; off; off >>= 1) lsum += __shfl_down_sync(0xffffffffu, lsum, off);
    if (lane == 0) lred[w] = lsum;
    __syncthreads();
    if (tid == 0) {
        float t = 0.f;
        #pragma unroll
        for (int ww = 0; ww < 4; ww++) t += lred[ww];
        atomicAdd(&g_loss, t);
    }
}

// ---------------------------------------------------------------------------
__global__ void vq_finalize(const float* __restrict__ ema_cs, float* __restrict__ out) {
    int k = threadIdx.x;  // 1024 threads
    float pre = ema_cs[k] * DECAY + OMD * g_counts[k];
    __shared__ float sred[32];
    float v = pre;
    int lane = k & 31, wid = k >> 5;
    for (int off = 16; off; off >>= 1) v += __shfl_down_sync(0xffffffffu, v, off);
    if (lane == 0) sred[wid] = v;
    __syncthreads();
    if (wid == 0) {
        float t = sred[lane];
        for (int off = 16; off; off >>= 1) t += __shfl_down_sync(0xffffffffu, t, off);
        if (lane == 0) sred[0] = t;
    }
    __syncthreads();
    float n = sred[0];
    float cs = (pre + EPS) / (n + KEPS) * n;
    out[CS_OFF + k] = cs;
    g_cs[k] = cs;
    if (k == 0) out[LOSS_OFF] = 0.25f * g_loss / (float)(NROWS * DDIM);
}

__global__ void vq_emaw(const float* __restrict__ ema_w, float* __restrict__ out) {
    int i = blockIdx.x * 256 + threadIdx.x;   // < K*D
    int k = i >> 8;
    float w = ema_w[i] * DECAY + OMD * g_dw[i];
    out[EMAW_OFF + i] = w;
    out[EMB_OFF + i] = w / g_cs[k];
}

// ---------------------------------------------------------------------------
extern "C" void kernel_launch(void* const* d_in, const int* in_sizes, int n_in,
                              void* d_out, int out_size) {
    const float* z      = (const float*)d_in[0];  // [32,1024,256]
    const float* emb    = (const float*)d_in[1];  // [1024,256]
    const float* ema_cs = (const float*)d_in[2];  // [1024]
    const float* ema_w  = (const float*)d_in[3];  // [1024,256]
    float* out = (float*)d_out;
    (void)in_sizes; (void)n_in; (void)out_size;

    cudaFuncSetAttribute(vq_main, cudaFuncAttributeMaxDynamicSharedMemorySize, SMEM_BYTES);

    vq_init<<<(KCODES * DDIM + 255) / 256, 256>>>();            // 1
    vq_e2<<<KCODES, 256>>>(emb);                                // 2
    vq_nop<<<1, 32>>>();                                        // 3
    vq_main<<<NROWS / BM, NTHR, SMEM_BYTES>>>(z, emb, out + Q_OFF, out + IDX_OFF);  // 4
    vq_finalize<<<1, 1024>>>(ema_cs, out);                      // 5
    vq_emaw<<<KCODES * DDIM / 256, 256>>>(ema_w, out);          // 6
}

// round 13
// speedup vs baseline: 12.2361x; 1.1273x over previous
#include <cuda_runtime.h>
#include <cstdint>
#include <cstddef>

// Problem constants
#define NROWS 32768          // B*T
#define DDIM  256
#define KCODES 1024

// Output layout (float32 concat of reference tuple)
#define Q_OFF    ((size_t)0)
#define LOSS_OFF ((size_t)8388608)
#define IDX_OFF  ((size_t)8388609)
#define CS_OFF   ((size_t)8421377)
#define EMAW_OFF ((size_t)8422401)
#define EMB_OFF  ((size_t)8684545)

#define DECAY 0.99f
#define OMD   ((float)(1.0 - 0.99))
#define EPS   1e-5f
#define KEPS  (1024.0f * 1e-5f)

// Tiling: BM=64 rows/CTA, 128 thr (4 warps), warp = 16 rows x 128 codes,
// thread = 8 rows x 8 codes.
#define BM 64
#define NTHR 128
#define ZS 66                      // zsp row stride in float2 (16B aligned)
#define ZSP_BYTES (128*ZS*8)       // 67584
#define DST 8                      // d2 per e-stage
#define NST 16                     // stages per k-chunk
#define NKC 8
#define NSTOT (NKC*NST)            // 128 total stages
#define NBUF 4                     // cp.async ring depth
#define EST_F4 (4*128)             // float4 per stage buffer (8 KB)
#define EST_BYTES (NBUF*EST_F4*16) // 32768
#define SMEM_BYTES (ZSP_BYTES + EST_BYTES + BM*4 + BM*4 + 4*4)   // 100880

// Scratch (allocation-free rule: __device__ globals)
__device__ __align__(16) float g_e2[KCODES];
__device__ float g_counts[KCODES];
__device__ float g_dw[KCODES * DDIM];
__device__ float g_loss;
__device__ float g_cs[KCODES];

// ---------------------------------------------------------------------------
// packed fp32x2 FMA (PTX-only pattern; doubles FFMA throughput on sm_103a)
__device__ __forceinline__ void ffma2(float2 &d, float2 a, float2 b) {
    unsigned long long dd = *reinterpret_cast<unsigned long long*>(&d);
    unsigned long long aa = *reinterpret_cast<unsigned long long*>(&a);
    unsigned long long bb = *reinterpret_cast<unsigned long long*>(&b);
    asm("fma.rn.f32x2 %0, %1, %2, %0;" : "+l"(dd) : "l"(aa), "l"(bb));
    d = *reinterpret_cast<float2*>(&dd);
}

__device__ __forceinline__ uint32_t smem_u32(const void* p) {
    uint32_t a;
    asm("{ .reg .u64 t; cvta.to.shared.u64 t, %1; cvt.u32.u64 %0, t; }" : "=r"(a) : "l"(p));
    return a;
}
__device__ __forceinline__ void cp_async16(uint32_t dst, const void* src) {
    asm volatile("cp.async.cg.shared.global [%0], [%1], 16;" :: "r"(dst), "l"(src) : "memory");
}
#define CP_COMMIT()  asm volatile("cp.async.commit_group;" ::: "memory")
#define CP_WAIT2()   asm volatile("cp.async.wait_group 2;" ::: "memory")

// ---------------------------------------------------------------------------
__global__ void vq_init() {
    int i = blockIdx.x * blockDim.x + threadIdx.x;
    if (i < KCODES * DDIM) g_dw[i] = 0.0f;
    if (i < KCODES) g_counts[i] = 0.0f;
    if (i == 0) g_loss = 0.0f;
}

__global__ void vq_nop() {}   // keeps vq_main in the ncu -s5 profiling slot

__global__ void vq_e2(const float* __restrict__ emb) {
    int k = blockIdx.x;
    float v = emb[k * DDIM + threadIdx.x];
    v *= v;
    for (int off = 16; off; off >>= 1) v += __shfl_down_sync(0xffffffffu, v, off);
    __shared__ float red[8];
    int lane = threadIdx.x & 31, wid = threadIdx.x >> 5;
    if (lane == 0) red[wid] = v;
    __syncthreads();
    if (threadIdx.x == 0) {
        float t = 0.f;
        #pragma unroll
        for (int w = 0; w < 8; w++) t += red[w];
        g_e2[k] = t;
    }
}

// ---------------------------------------------------------------------------
// stage S: e chunk (kc = S>>4, st = S&15): 128 codes x 8 d2, code-major float4s
// smem idx = buf*512 + jj*128 + (code ^ ((code>>3)&7))
__device__ __forceinline__ void issue_stage(uint32_t est_u32, const float4* embv,
                                            int S, int tid) {
    int kc = S >> 4, st = S & 15;
    const float4* src = embv + (size_t)(kc * 128 + tid) * 64 + st * 4;
    uint32_t dst = est_u32 + (uint32_t)(((S & (NBUF - 1)) * EST_F4
                                        + (tid ^ ((tid >> 3) & 7))) * 16);
    #pragma unroll
    for (int jj = 0; jj < 4; jj++)
        cp_async16(dst + jj * 128 * 16, src + jj);
}

__global__ __launch_bounds__(NTHR, 2)
void vq_main(const float* __restrict__ z, const float* __restrict__ emb,
             float* __restrict__ outq, float* __restrict__ outidx) {
    extern __shared__ char smem_raw[];
    float2* zsp  = (float2*)smem_raw;                         // z tile, d-pair packed, transposed
    float4* est  = (float4*)(smem_raw + ZSP_BYTES);           // cp.async e ring
    float*  sa   = (float*)(smem_raw + ZSP_BYTES + EST_BYTES);// [BM] ||z_row||^2
    int*    sidx = (int*)(sa + BM);                           // [BM]
    float*  lred = (float*)(sidx + BM);                       // [4]

    const int tid  = threadIdx.x;
    const int lane = tid & 31;
    const int w    = tid >> 5;               // warp -> rows w*16..w*16+15
    const int lr   = lane >> 4;              // 8-row subgroup
    const int lc   = lane & 15;              // 8-code group
    const int slc  = lc & 7;
    const int row0 = blockIdx.x * BM;
    const float4* zv4  = (const float4*)z;
    const float4* embv = (const float4*)emb;
    const uint32_t est_u32 = smem_u32(est);

    // --- load z tile transposed & d-pair packed ---------------------------
    for (int idx = tid; idx < BM * (DDIM / 4); idx += NTHR) {
        int m = idx >> 6;
        int f4 = idx & 63;
        float4 v = zv4[(size_t)(row0 + m) * 64 + f4];
        zsp[(2 * f4) * ZS + m]     = make_float2(v.x, v.y);
        zsp[(2 * f4 + 1) * ZS + m] = make_float2(v.z, v.w);
    }
    // prologue: issue e stages 0..2
    #pragma unroll
    for (int p = 0; p < 3; p++) { issue_stage(est_u32, embv, p, tid); CP_COMMIT(); }
    __syncthreads();

    // ||z||^2 per row (warp-owned 16 rows)
    for (int i = 0; i < 16; i++) {
        int row = w * 16 + i;
        float s = 0.f;
        #pragma unroll
        for (int u = 0; u < 4; u++) {
            float2 p = zsp[(lane + u * 32) * ZS + row];
            s = fmaf(p.x, p.x, fmaf(p.y, p.y, s));
        }
        for (int off = 16; off; off >>= 1) s += __shfl_down_sync(0xffffffffu, s, off);
        if (lane == 0) sa[row] = s;
    }
    __syncthreads();
    float anr[8];
    #pragma unroll
    for (int i = 0; i < 8; i++) anr[i] = sa[w * 16 + lr * 8 + i];

    // --- main loop --------------------------------------------------------
    float bestv[8]; int besti[8];
    #pragma unroll
    for (int i = 0; i < 8; i++) { bestv[i] = 3.402823466e38f; besti[i] = 0; }
    float2 acc[8][8];
    #pragma unroll
    for (int i = 0; i < 8; i++)
        #pragma unroll
        for (int j = 0; j < 8; j++) acc[i][j] = make_float2(0.f, 0.f);

    #pragma unroll 1
    for (int S = 0; S < NSTOT; S++) {
        const int kc = S >> 4, st = S & 15;
        CP_WAIT2();                 // stage S resident
        __syncthreads();            // visible to all; prior buffer reuse safe
        if (S + 3 < NSTOT) issue_stage(est_u32, embv, S + 3, tid);
        CP_COMMIT();                // empty group when no issue keeps counts sane

        const float4* ebb = est + (S & (NBUF - 1)) * EST_F4;
        #pragma unroll
        for (int jj = 0; jj < 4; jj++) {
            float4 b4[8];
            #pragma unroll
            for (int j = 0; j < 8; j++)
                b4[j] = ebb[jj * 128 + 8 * lc + (j ^ slc)];
            #pragma unroll
            for (int h = 0; h < 2; h++) {
                const float2* zr = zsp + (st * 8 + jj * 2 + h) * ZS + w * 16 + lr * 8;
                float2 a2[8];
                #pragma unroll
                for (int i = 0; i < 8; i += 2) {
                    float4 t = *reinterpret_cast<const float4*>(zr + i);
                    a2[i]     = make_float2(t.x, t.y);
                    a2[i + 1] = make_float2(t.z, t.w);
                }
                #pragma unroll
                for (int i = 0; i < 8; i++)
                    #pragma unroll
                    for (int j = 0; j < 8; j++) {
                        float2 bb = h ? make_float2(b4[j].z, b4[j].w)
                                      : make_float2(b4[j].x, b4[j].y);
                        ffma2(acc[i][j], a2[i], bb);
                    }
            }
        }

        if (st == NST - 1) {
            // scores for this k-chunk, replicating jax rounding:
            // dist = fl( fl(||z||^2 + ||e||^2) - fl(2*dot) )
            float4 e2lo = *reinterpret_cast<const float4*>(&g_e2[kc * 128 + lc * 8]);
            float4 e2hi = *reinterpret_cast<const float4*>(&g_e2[kc * 128 + lc * 8 + 4]);
            float e2a[8] = { e2lo.x, e2lo.y, e2lo.z, e2lo.w,
                             e2hi.x, e2hi.y, e2hi.z, e2hi.w };
            #pragma unroll
            for (int i = 0; i < 8; i++) {
                float an = anr[i];
                #pragma unroll
                for (int j = 0; j < 8; j++) {
                    float dot = acc[i][j].x + acc[i][j].y;
                    float t1 = an + e2a[j];
                    float sc = t1 - 2.0f * dot;
                    int code = kc * 128 + lc * 8 + j;
                    if (sc < bestv[i]) { bestv[i] = sc; besti[i] = code; }
                    acc[i][j] = make_float2(0.f, 0.f);
                }
            }
        }
    }

    // --- argmin reduce across the 16 lc lanes (first-min tie-break) -------
    #pragma unroll
    for (int i = 0; i < 8; i++) {
        float v = bestv[i]; int ix = besti[i];
        #pragma unroll
        for (int off = 8; off; off >>= 1) {
            float ov = __shfl_down_sync(0xffffffffu, v, off, 16);
            int   oi = __shfl_down_sync(0xffffffffu, ix, off, 16);
            if (ov < v || (ov == v && oi < ix)) { v = ov; ix = oi; }
        }
        if (lc == 0) {
            int row = w * 16 + lr * 8 + i;
            sidx[row] = ix;
            outidx[row0 + row] = (float)ix;
        }
    }
    __syncthreads();

    // --- epilogue: quantized gather, loss, counts, dw scatter -------------
    float lsum = 0.f;
    const int d0 = tid * 2;   // 128 threads x 2 floats = DDIM
    for (int r = 0; r < BM; r++) {
        int code = sidx[r];
        size_t go = (size_t)(row0 + r) * DDIM + d0;
        float2 q  = *reinterpret_cast<const float2*>(&emb[(size_t)code * DDIM + d0]);
        float2 zv = *reinterpret_cast<const float2*>(&z[go]);
        *reinterpret_cast<float2*>(&outq[go]) = q;
        float dx = zv.x - q.x, dy = zv.y - q.y;
        lsum = fmaf(dx, dx, fmaf(dy, dy, lsum));
        atomicAdd(&g_dw[code * DDIM + d0], zv.x);
        atomicAdd(&g_dw[code * DDIM + d0 + 1], zv.y);
    }
    if (tid < BM) atomicAdd(&g_counts[sidx[tid]], 1.0f);

    for (int off = 16; off; off >>= 1) lsum += __shfl_down_sync(0xffffffffu, lsum, off);
    if (lane == 0) lred[w] = lsum;
    __syncthreads();
    if (tid == 0) {
        float t = 0.f;
        #pragma unroll
        for (int ww = 0; ww < 4; ww++) t += lred[ww];
        atomicAdd(&g_loss, t);
    }
}

// ---------------------------------------------------------------------------
__global__ void vq_finalize(const float* __restrict__ ema_cs, float* __restrict__ out) {
    int k = threadIdx.x;  // 1024 threads
    float pre = ema_cs[k] * DECAY + OMD * g_counts[k];
    __shared__ float sred[32];
    float v = pre;
    int lane = k & 31, wid = k >> 5;
    for (int off = 16; off; off >>= 1) v += __shfl_down_sync(0xffffffffu, v, off);
    if (lane == 0) sred[wid] = v;
    __syncthreads();
    if (wid == 0) {
        float t = sred[lane];
        for (int off = 16; off; off >>= 1) t += __shfl_down_sync(0xffffffffu, t, off);
        if (lane == 0) sred[0] = t;
    }
    __syncthreads();
    float n = sred[0];
    float cs = (pre + EPS) / (n + KEPS) * n;
    out[CS_OFF + k] = cs;
    g_cs[k] = cs;
    if (k == 0) out[LOSS_OFF] = 0.25f * g_loss / (float)(NROWS * DDIM);
}

__global__ void vq_emaw(const float* __restrict__ ema_w, float* __restrict__ out) {
    int i = blockIdx.x * 256 + threadIdx.x;   // < K*D
    int k = i >> 8;
    float w = ema_w[i] * DECAY + OMD * g_dw[i];
    out[EMAW_OFF + i] = w;
    out[EMB_OFF + i] = w / g_cs[k];
}

// ---------------------------------------------------------------------------
extern "C" void kernel_launch(void* const* d_in, const int* in_sizes, int n_in,
                              void* d_out, int out_size) {
    const float* z      = (const float*)d_in[0];  // [32,1024,256]
    const float* emb    = (const float*)d_in[1];  // [1024,256]
    const float* ema_cs = (const float*)d_in[2];  // [1024]
    const float* ema_w  = (const float*)d_in[3];  // [1024,256]
    float* out = (float*)d_out;
    (void)in_sizes; (void)n_in; (void)out_size;

    cudaFuncSetAttribute(vq_main, cudaFuncAttributeMaxDynamicSharedMemorySize, SMEM_BYTES);

    vq_init<<<(KCODES * DDIM + 255) / 256, 256>>>();            // 1
    vq_e2<<<KCODES, 256>>>(emb);                                // 2
    vq_nop<<<1, 32>>>();                                        // 3
    vq_main<<<NROWS / BM, NTHR, SMEM_BYTES>>>(z, emb, out + Q_OFF, out + IDX_OFF);  // 4
    vq_finalize<<<1, 1024>>>(ema_cs, out);                      // 5
    vq_emaw<<<KCODES * DDIM / 256, 256>>>(ema_w, out);          // 6
}